// round 13
// baseline (speedup 1.0000x reference)
#include <cuda_runtime.h>
#include <cuda_fp16.h>
#include <stdint.h>

// ---------------------------------------------------------------------------
// Problem constants
// ---------------------------------------------------------------------------
#define NB   8
#define NP   8192
#define NM   (NB * NP)          // 65536 rows
#define NK   128                // codes per record
#define ND   128                // code dim
#define XK   192                // padded x K-dim (131 valid, rest zero) — 3 x 64
#define PPB  128                // stage-1 points per block

// One dynamic-smem symbol for the whole TU (R8 lesson: types must agree)
extern __shared__ unsigned char dynsm[];

// ---------------------------------------------------------------------------
// Scratch: single fp16 planes for x and h activations; fp16 weights.
// ---------------------------------------------------------------------------
__device__ __half g_x [(size_t)NM * XK];
__device__ __half g_h1[(size_t)NM * 2048];
__device__ __half g_h2[(size_t)NM * 1024];
__device__ __half g_h3[(size_t)NM * 512];
__device__ __half g_h4[(size_t)NM * 256];
__device__ __half g_h5[(size_t)NM * 128];
// fp16 weights: sum of (K1+192)*N over 5 layers = 3,547,136
__device__ __half g_wq[3600000];

// ---------------------------------------------------------------------------
// Helpers
// ---------------------------------------------------------------------------
__device__ __forceinline__ uint32_t smem_u32(const void* p)
{
    return (uint32_t)__cvta_generic_to_shared(p);
}

template<int Ngrp> __device__ __forceinline__ void cp_wait()
{
    asm volatile("cp.async.wait_group %0;\n" :: "n"(Ngrp));
}

#define CP16(dst_u32, src_ptr) \
    asm volatile("cp.async.cg.shared.global [%0], [%1], 16;\n" :: "r"(dst_u32), "l"(src_ptr))

__device__ __forceinline__ void ldsm_x4(uint32_t* r, uint32_t addr)
{
    asm volatile("ldmatrix.sync.aligned.m8n8.x4.shared.b16 {%0,%1,%2,%3}, [%4];\n"
                 : "=r"(r[0]), "=r"(r[1]), "=r"(r[2]), "=r"(r[3]) : "r"(addr));
}

__device__ __forceinline__ void ldsm_x4_t(uint32_t* r, uint32_t addr)
{
    asm volatile("ldmatrix.sync.aligned.m8n8.x4.trans.shared.b16 {%0,%1,%2,%3}, [%4];\n"
                 : "=r"(r[0]), "=r"(r[1]), "=r"(r[2]), "=r"(r[3]) : "r"(addr));
}

__device__ __forceinline__ void mma16816(float* d, const uint32_t* a, uint32_t b0, uint32_t b1)
{
    asm volatile(
        "mma.sync.aligned.m16n8k16.row.col.f32.f16.f16.f32 "
        "{%0,%1,%2,%3}, {%4,%5,%6,%7}, {%8,%9}, {%0,%1,%2,%3};\n"
        : "+f"(d[0]), "+f"(d[1]), "+f"(d[2]), "+f"(d[3])
        : "r"(a[0]), "r"(a[1]), "r"(a[2]), "r"(a[3]), "r"(b0), "r"(b1));
}

// ---------------------------------------------------------------------------
// Stage 1: inverse-square-distance weighted code interpolation -> x plane
// x[m, 0:128] = weighted codes, x[m,128:131] = query point, 131..191 = 0
// ---------------------------------------------------------------------------
__global__ void stage1_kernel(const int* __restrict__ indices,
                              const float* __restrict__ qp,
                              const float* __restrict__ codes_pos,
                              const float* __restrict__ codes)
{
    float*  smem = reinterpret_cast<float*>(dynsm);
    float4* bc4  = reinterpret_cast<float4*>(smem);   // [128 codes][32 float4]
    float*  ws   = smem + NK * ND;                    // [8 warps][128] weights

    const int b   = blockIdx.x;
    const int rec = indices[b];

    const float4* csrc = reinterpret_cast<const float4*>(codes + (size_t)rec * NK * ND);
    for (int i = threadIdx.x; i < NK * (ND / 4); i += blockDim.x)
        bc4[i] = csrc[i];
    __syncthreads();

    const int warp = threadIdx.x >> 5;
    const int lane = threadIdx.x & 31;

    const float* pbase = codes_pos + (size_t)rec * NK * 3;
    float cpx[4], cpy[4], cpz[4];
#pragma unroll
    for (int t = 0; t < 4; t++) {
        int k = lane + 32 * t;
        cpx[t] = pbase[k * 3 + 0];
        cpy[t] = pbase[k * 3 + 1];
        cpz[t] = pbase[k * 3 + 2];
    }

    float* wsw = ws + warp * NK;
    const int p0 = blockIdx.y * PPB;

    for (int pi = warp; pi < PPB; pi += 8) {
        const int m = b * NP + p0 + pi;
        const float qx = qp[(size_t)m * 3 + 0];
        const float qy = qp[(size_t)m * 3 + 1];
        const float qz = qp[(size_t)m * 3 + 2];

        float wsum = 0.f;
#pragma unroll
        for (int t = 0; t < 4; t++) {
            float dx = qx - cpx[t], dy = qy - cpy[t], dz = qz - cpz[t];
            float sq = dx * dx + dy * dy + dz * dz + 1e-16f;
            float w  = 1.0f / sq;
            wsw[lane + 32 * t] = w;
            wsum += w;
        }
        __syncwarp();
#pragma unroll
        for (int o = 16; o > 0; o >>= 1)
            wsum += __shfl_xor_sync(0xffffffffu, wsum, o);

        float4 acc = make_float4(0.f, 0.f, 0.f, 0.f);
#pragma unroll 4
        for (int k = 0; k < NK; k++) {
            const float  w = wsw[k];
            const float4 c = bc4[k * 32 + lane];
            acc.x = fmaf(w, c.x, acc.x);
            acc.y = fmaf(w, c.y, acc.y);
            acc.z = fmaf(w, c.z, acc.z);
            acc.w = fmaf(w, c.w, acc.w);
        }
        const float inv = 1.0f / wsum;

        __half* xh = g_x + (size_t)m * XK;
        float v[4] = { acc.x * inv, acc.y * inv, acc.z * inv, acc.w * inv };
#pragma unroll
        for (int j = 0; j < 4; j++)
            xh[4 * lane + j] = __float2half(v[j]);

        // tail cols 128..191: query point then zeros
#pragma unroll
        for (int c = 128 + lane; c < XK; c += 32) {
            float q = (c == 128) ? qx : (c == 129) ? qy : (c == 130) ? qz : 0.f;
            xh[c] = __float2half(q);
        }
        __syncwarp();
    }
}

// ---------------------------------------------------------------------------
// Weight prep: fp32 W[K1+131, N] -> single fp16 plane, x-part padded to 192 rows
// ---------------------------------------------------------------------------
__global__ void prep_w(const float* __restrict__ W, int K1, int N,
                       __half* __restrict__ hh, __half* __restrict__ xh)
{
    const int idx = blockIdx.x * blockDim.x + threadIdx.x;
    const int tot = (K1 + XK) * N;
    if (idx >= tot) return;
    const int r = idx / N, n = idx - r * N;
    if (r < K1) {
        hh[(size_t)r * N + n] = __float2half(W[(size_t)r * N + n]);
    } else {
        const int r2 = r - K1;
        float v = (r2 < 131) ? W[(size_t)(K1 + r2) * N + n] : 0.f;
        xh[(size_t)r2 * N + n] = __float2half(v);
    }
}

// ---------------------------------------------------------------------------
// Segmented fp16 tensor-core GEMM, K-chunks of 64, cp.async double buffer.
//   Out[m,n] = act( h @ Wh + x @ Wx + bias )   (skip-concat via segments)
// CTA 128x128, 8 warps (32x64 each). Dynamic smem: 2 x (16K A + 16K B) = 64KB.
// A tile [128m x 64k]: rows 128B, phys = m*8 + (c ^ (m&7))  (uint4 units)
// B tile [64k x 128n]: rows 256B, phys = k*16 + (c ^ (k&7))
// ---------------------------------------------------------------------------
struct Seg { const __half* A; const __half* B; int lda; int kchunks; };
struct SegList { Seg s[3]; int n; };

#define ABUF_U4 1024            // 128*8 uint4 per A tile
#define BBUF_U4 1024            // 64*16 uint4 per B tile
#define STAGE_U4 2048           // per-stage uint4 (32KB)

__global__ __launch_bounds__(256, 2)
void mma_gemm(SegList SL, const float* __restrict__ bias, int N,
              __half* __restrict__ out)
{
    const int t    = threadIdx.x;
    const int lane = t & 31;
    const int w    = t >> 5;
    const int wm   = (w & 3) * 32;   // warp M offset in tile
    const int wn   = (w >> 2) * 64;  // warp N offset in tile

    const int n0 = blockIdx.x * 128;
    const int m0 = blockIdx.y * 128;

    // A loader: thread -> row am (2 threads/row), 4 consecutive uint4 cols
    const int am  = t >> 1;
    const int ac0 = (t & 1) * 4;
    // B loader: thread -> row bk (4 threads/row), 4 consecutive uint4 cols
    const int bk  = t >> 2;
    const int bc0 = (t & 3) * 4;

    const uint32_t sb = smem_u32(dynsm);

    int tot = 0;
#pragma unroll
    for (int s = 0; s < 3; s++) if (s < SL.n) tot += SL.s[s].kchunks;

    float d[2][8][4];
#pragma unroll
    for (int i = 0; i < 2; i++)
#pragma unroll
        for (int j = 0; j < 8; j++)
#pragma unroll
            for (int q = 0; q < 4; q++) d[i][j][q] = 0.f;

    int ls = 0, lc = 0;   // next chunk to load: segment / chunk-in-segment

    auto issue = [&](int buf) {
        const Seg sg = SL.s[ls];
        const uint32_t ab = sb + (uint32_t)buf * STAGE_U4 * 16;
        const uint32_t bb = ab + ABUF_U4 * 16;
        const __half* Ap = sg.A + (size_t)(m0 + am) * sg.lda + lc * 64 + ac0 * 8;
        const __half* Bp = sg.B + (size_t)(lc * 64 + bk) * N + n0 + bc0 * 8;
#pragma unroll
        for (int j = 0; j < 4; j++) {
            const uint32_t pa = (uint32_t)(am * 8 + ((ac0 + j) ^ (am & 7)));
            CP16(ab + pa * 16, Ap + j * 8);
            const uint32_t pb = (uint32_t)(bk * 16 + ((bc0 + j) ^ (bk & 7)));
            CP16(bb + pb * 16, Bp + j * 8);
        }
        asm volatile("cp.async.commit_group;\n");
        if (++lc == sg.kchunks) { lc = 0; ++ls; }
    };

    issue(0);
    int issued = 1;

    for (int i = 0; i < tot; i++) {
        const int buf = i & 1;
        if (issued < tot) { issue(issued & 1); issued++; cp_wait<1>(); }
        else              { cp_wait<0>(); }
        __syncthreads();

        const uint32_t ab = sb + (uint32_t)buf * STAGE_U4 * 16;
        const uint32_t bb = ab + ABUF_U4 * 16;

#pragma unroll
        for (int kk = 0; kk < 4; kk++) {
            // A fragments: 2 m16 tiles
            uint32_t a[2][4];
#pragma unroll
            for (int mi = 0; mi < 2; mi++) {
                const int mrow = wm + mi * 16 + (lane & 15);
                const int c    = kk * 2 + (lane >> 4);
                const int phys = mrow * 8 + (c ^ (mrow & 7));
                ldsm_x4(a[mi], ab + (uint32_t)phys * 16);
            }
            // B fragments (4 groups of n16) + MMAs
#pragma unroll
            for (int j = 0; j < 4; j++) {
                uint32_t bfr[4];
                const int krow = kk * 16 + (lane & 15);
                const int cn   = (wn >> 3) + j * 2 + (lane >> 4);
                const int phys = krow * 16 + (cn ^ (krow & 7));
                ldsm_x4_t(bfr, bb + (uint32_t)phys * 16);
#pragma unroll
                for (int mi = 0; mi < 2; mi++) {
                    mma16816(d[mi][2 * j],     a[mi], bfr[0], bfr[1]);
                    mma16816(d[mi][2 * j + 1], a[mi], bfr[2], bfr[3]);
                }
            }
        }
        __syncthreads();
    }

    // ---- epilogue: bias + leaky-relu + fp16 store ----
#pragma unroll
    for (int mi = 0; mi < 2; mi++) {
#pragma unroll
        for (int j = 0; j < 8; j++) {
            const int col  = n0 + wn + j * 8 + (lane & 3) * 2;
            const float b0 = bias[col], b1 = bias[col + 1];
#pragma unroll
            for (int rh = 0; rh < 2; rh++) {
                const int row = m0 + wm + mi * 16 + (lane >> 2) + rh * 8;
                float v0 = d[mi][j][2 * rh]     + b0;
                float v1 = d[mi][j][2 * rh + 1] + b1;
                v0 = (v0 > 0.f) ? v0 : 0.02f * v0;
                v1 = (v1 > 0.f) ? v1 : 0.02f * v1;
                *reinterpret_cast<__half2*>(out + (size_t)row * N + col) =
                    __halves2half2(__float2half(v0), __float2half(v1));
            }
        }
    }
}

// ---------------------------------------------------------------------------
// Final layer: out[m] = h5[m,:] . W6 + b6   (128 -> 1)
// ---------------------------------------------------------------------------
__global__ void final_kernel(const __half* __restrict__ h5,
                             const float* __restrict__ W6,
                             const float* __restrict__ b6,
                             float* __restrict__ out)
{
    const int warp = threadIdx.x >> 5;
    const int lane = threadIdx.x & 31;
    const int m = blockIdx.x * 8 + warp;

    float s = 0.f;
#pragma unroll
    for (int j = 0; j < 4; j++) {
        const int c = 4 * lane + j;
        s = fmaf(__half2float(h5[(size_t)m * 128 + c]), W6[c], s);
    }
#pragma unroll
    for (int o = 16; o > 0; o >>= 1)
        s += __shfl_xor_sync(0xffffffffu, s, o);
    if (lane == 0) out[m] = s + b6[0];
}

// ---------------------------------------------------------------------------
// Launch
// ---------------------------------------------------------------------------
extern "C" void kernel_launch(void* const* d_in, const int* in_sizes, int n_in,
                              void* d_out, int out_size)
{
    (void)in_sizes; (void)n_in; (void)out_size;

    const int*   indices = (const int*)  d_in[0];
    const float* qp      = (const float*)d_in[1];
    const float* cpos    = (const float*)d_in[2];
    const float* codes   = (const float*)d_in[3];
    const float* W1 = (const float*)d_in[4];  const float* b1 = (const float*)d_in[5];
    const float* W2 = (const float*)d_in[6];  const float* b2 = (const float*)d_in[7];
    const float* W3 = (const float*)d_in[8];  const float* b3 = (const float*)d_in[9];
    const float* W4 = (const float*)d_in[10]; const float* b4 = (const float*)d_in[11];
    const float* W5 = (const float*)d_in[12]; const float* b5 = (const float*)d_in[13];
    const float* W6 = (const float*)d_in[14]; const float* b6 = (const float*)d_in[15];
    float* out = (float*)d_out;

    __half *x, *h1, *h2, *h3, *h4, *h5, *wq;
    cudaGetSymbolAddress((void**)&x,  g_x);
    cudaGetSymbolAddress((void**)&h1, g_h1); cudaGetSymbolAddress((void**)&h2, g_h2);
    cudaGetSymbolAddress((void**)&h3, g_h3); cudaGetSymbolAddress((void**)&h4, g_h4);
    cudaGetSymbolAddress((void**)&h5, g_h5); cudaGetSymbolAddress((void**)&wq, g_wq);

    // weight plane offsets
    size_t off = 0;
    auto take = [&](size_t nelem) { __half* p = wq + off; off += nelem; return p; };
    __half* w1x = take((size_t)XK * 2048);
    __half* w2h = take((size_t)2048 * 1024);
    __half* w2x = take((size_t)XK * 1024);
    __half* w3h = take((size_t)1024 * 512);
    __half* w3x = take((size_t)XK * 512);
    __half* w4h = take((size_t)512 * 256);
    __half* w4x = take((size_t)XK * 256);
    __half* w5h = take((size_t)256 * 128);
    __half* w5x = take((size_t)XK * 128);

    // weight prep (fp32 -> fp16, x-part padded to 192 rows)
    auto prep = [&](const float* W, int K1, int N, __half* hh, __half* xh) {
        int tot = (K1 + XK) * N;
        prep_w<<<(tot + 255) / 256, 256>>>(W, K1, N, hh, xh);
    };
    prep(W1, 0,    2048, w1x, w1x);
    prep(W2, 2048, 1024, w2h, w2x);
    prep(W3, 1024, 512,  w3h, w3x);
    prep(W4, 512,  256,  w4h, w4x);
    prep(W5, 256,  128,  w5h, w5x);

    // stage 1
    const int s1_smem = NK * ND * (int)sizeof(float) + 8 * NK * (int)sizeof(float);
    cudaFuncSetAttribute(stage1_kernel, cudaFuncAttributeMaxDynamicSharedMemorySize, s1_smem);
    stage1_kernel<<<dim3(NB, NP / PPB), 256, s1_smem>>>(indices, qp, cpos, codes);

    // GEMM layers
    const int GSMEM = 2 * STAGE_U4 * 16;   // 65536
    cudaFuncSetAttribute(mma_gemm, cudaFuncAttributeMaxDynamicSharedMemorySize, GSMEM);

    auto run = [&](int N, const float* bias,
                   __half* Ah, int K1, __half* Wh, __half* Wx, __half* Oh) {
        SegList SL;
        int n = 0;
        if (K1 > 0) SL.s[n++] = { Ah, Wh, K1, K1 >> 6 };
        SL.s[n++] = { x, Wx, XK, XK >> 6 };
        SL.n = n;
        mma_gemm<<<dim3(N / 128, NM / 128), 256, GSMEM>>>(SL, bias, N, Oh);
    };

    run(2048, b1, nullptr, 0,    nullptr, w1x, h1);
    run(1024, b2, h1, 2048, w2h, w2x, h2);
    run(512,  b3, h2, 1024, w3h, w3x, h3);
    run(256,  b4, h3, 512,  w4h, w4x, h4);
    run(128,  b5, h4, 256,  w5h, w5x, h5);

    // Final 128 -> 1 dot
    final_kernel<<<NM / 8, 256>>>(h5, W6, b6, out);
}

// round 14
// speedup vs baseline: 1.2394x; 1.2394x over previous
#include <cuda_runtime.h>
#include <cuda_fp16.h>
#include <stdint.h>

// ---------------------------------------------------------------------------
// Problem constants
// ---------------------------------------------------------------------------
#define NB   8
#define NP   8192
#define NM   (NB * NP)          // 65536 rows
#define NK   128                // codes per record
#define ND   128                // code dim
#define XK   160                // padded x K-dim (131 valid, rest zero) — mult of 32
#define PPB  128                // stage-1 points per block

// ---------------------------------------------------------------------------
// Scratch: single fp16 planes for x and h activations; fp16 weights.
// ---------------------------------------------------------------------------
__device__ __half g_x [(size_t)NM * XK];
__device__ __half g_h1[(size_t)NM * 2048];
__device__ __half g_h2[(size_t)NM * 1024];
__device__ __half g_h3[(size_t)NM * 512];
__device__ __half g_h4[(size_t)NM * 256];
__device__ __half g_h5[(size_t)NM * 128];
// fp16 weights (single plane): sum of (K1+160)*N over 5 layers = 3,420,160
__device__ __half g_wq[3500000];

// ---------------------------------------------------------------------------
// Helpers
// ---------------------------------------------------------------------------
__device__ __forceinline__ uint32_t smem_u32(const void* p)
{
    return (uint32_t)__cvta_generic_to_shared(p);
}

template<int Ngrp> __device__ __forceinline__ void cp_wait()
{
    asm volatile("cp.async.wait_group %0;\n" :: "n"(Ngrp));
}

#define CP16(dst_u32, src_ptr) \
    asm volatile("cp.async.cg.shared.global [%0], [%1], 16;\n" :: "r"(dst_u32), "l"(src_ptr))

__device__ __forceinline__ void ldsm_x4(uint32_t* r, uint32_t addr)
{
    asm volatile("ldmatrix.sync.aligned.m8n8.x4.shared.b16 {%0,%1,%2,%3}, [%4];\n"
                 : "=r"(r[0]), "=r"(r[1]), "=r"(r[2]), "=r"(r[3]) : "r"(addr));
}

__device__ __forceinline__ void ldsm_x4_t(uint32_t* r, uint32_t addr)
{
    asm volatile("ldmatrix.sync.aligned.m8n8.x4.trans.shared.b16 {%0,%1,%2,%3}, [%4];\n"
                 : "=r"(r[0]), "=r"(r[1]), "=r"(r[2]), "=r"(r[3]) : "r"(addr));
}

__device__ __forceinline__ void mma16816(float* d, const uint32_t* a, uint32_t b0, uint32_t b1)
{
    asm volatile(
        "mma.sync.aligned.m16n8k16.row.col.f32.f16.f16.f32 "
        "{%0,%1,%2,%3}, {%4,%5,%6,%7}, {%8,%9}, {%0,%1,%2,%3};\n"
        : "+f"(d[0]), "+f"(d[1]), "+f"(d[2]), "+f"(d[3])
        : "r"(a[0]), "r"(a[1]), "r"(a[2]), "r"(a[3]), "r"(b0), "r"(b1));
}

// ---------------------------------------------------------------------------
// Stage 1: inverse-square-distance weighted code interpolation -> x plane
// x[m, 0:128] = weighted codes, x[m,128:131] = query point, 131..159 = 0
// ---------------------------------------------------------------------------
__global__ void stage1_kernel(const int* __restrict__ indices,
                              const float* __restrict__ qp,
                              const float* __restrict__ codes_pos,
                              const float* __restrict__ codes)
{
    extern __shared__ float smem[];
    float4* bc4 = reinterpret_cast<float4*>(smem);   // [128 codes][32 float4]
    float*  ws  = smem + NK * ND;                    // [8 warps][128] weights

    const int b   = blockIdx.x;
    const int rec = indices[b];

    const float4* csrc = reinterpret_cast<const float4*>(codes + (size_t)rec * NK * ND);
    for (int i = threadIdx.x; i < NK * (ND / 4); i += blockDim.x)
        bc4[i] = csrc[i];
    __syncthreads();

    const int warp = threadIdx.x >> 5;
    const int lane = threadIdx.x & 31;

    const float* pbase = codes_pos + (size_t)rec * NK * 3;
    float cpx[4], cpy[4], cpz[4];
#pragma unroll
    for (int t = 0; t < 4; t++) {
        int k = lane + 32 * t;
        cpx[t] = pbase[k * 3 + 0];
        cpy[t] = pbase[k * 3 + 1];
        cpz[t] = pbase[k * 3 + 2];
    }

    float* wsw = ws + warp * NK;
    const int p0 = blockIdx.y * PPB;

    for (int pi = warp; pi < PPB; pi += 8) {
        const int m = b * NP + p0 + pi;
        const float qx = qp[(size_t)m * 3 + 0];
        const float qy = qp[(size_t)m * 3 + 1];
        const float qz = qp[(size_t)m * 3 + 2];

        float wsum = 0.f;
#pragma unroll
        for (int t = 0; t < 4; t++) {
            float dx = qx - cpx[t], dy = qy - cpy[t], dz = qz - cpz[t];
            float sq = dx * dx + dy * dy + dz * dz + 1e-16f;
            float w  = 1.0f / sq;
            wsw[lane + 32 * t] = w;
            wsum += w;
        }
        __syncwarp();
#pragma unroll
        for (int o = 16; o > 0; o >>= 1)
            wsum += __shfl_xor_sync(0xffffffffu, wsum, o);

        float4 acc = make_float4(0.f, 0.f, 0.f, 0.f);
#pragma unroll 4
        for (int k = 0; k < NK; k++) {
            const float  w = wsw[k];
            const float4 c = bc4[k * 32 + lane];
            acc.x = fmaf(w, c.x, acc.x);
            acc.y = fmaf(w, c.y, acc.y);
            acc.z = fmaf(w, c.z, acc.z);
            acc.w = fmaf(w, c.w, acc.w);
        }
        const float inv = 1.0f / wsum;

        __half* xh = g_x + (size_t)m * XK;
        float v[4] = { acc.x * inv, acc.y * inv, acc.z * inv, acc.w * inv };
#pragma unroll
        for (int j = 0; j < 4; j++)
            xh[4 * lane + j] = __float2half(v[j]);

        // tail cols 128..159: query point then zeros (one col per lane)
        {
            const int c = 128 + lane;
            float q = 0.f;
            if (lane == 0) q = qx; else if (lane == 1) q = qy; else if (lane == 2) q = qz;
            xh[c] = __float2half(q);
        }
        __syncwarp();
    }
}

// ---------------------------------------------------------------------------
// Weight prep: fp32 W[K1+131, N] -> single fp16 plane, x-part padded to 160 rows
// Layout preserved: hh[k, n] (K1 x N), xh[k2, n] (XK x N)
// ---------------------------------------------------------------------------
__global__ void prep_w(const float* __restrict__ W, int K1, int N,
                       __half* __restrict__ hh, __half* __restrict__ xh)
{
    const int idx = blockIdx.x * blockDim.x + threadIdx.x;
    const int tot = (K1 + XK) * N;
    if (idx >= tot) return;
    const int r = idx / N, n = idx - r * N;
    if (r < K1) {
        hh[(size_t)r * N + n] = __float2half(W[(size_t)r * N + n]);
    } else {
        const int r2 = r - K1;
        float v = (r2 < 131) ? W[(size_t)(K1 + r2) * N + n] : 0.f;
        xh[(size_t)r2 * N + n] = __float2half(v);
    }
}

// ---------------------------------------------------------------------------
// Segmented fp16 tensor-core GEMM with fused bias + leaky-relu + fp16 store.
//   Out[m,n] = act( h @ Wh + x @ Wx + bias )   (skip-concat via segments)
// CTA 128x128, 8 warps (32x64 each), K-chunks of 32, cp.async double buffer.
// (Proven R12 structure, unchanged; only the segment list shrank.)
// ---------------------------------------------------------------------------
struct Seg { const __half* A; const __half* B; int lda; int kchunks; };
struct SegList { Seg s[2]; int n; };

__global__ __launch_bounds__(256, 2)
void mma_gemm(SegList SL, const float* __restrict__ bias, int N,
              __half* __restrict__ out)
{
    __shared__ uint4 As4[2][512];   // [buf][m(128) x chunk(4)] xor-swizzled
    __shared__ uint4 Bs4[2][512];   // [buf][k(32) x chunk(16)] xor-swizzled

    const int t    = threadIdx.x;
    const int lane = t & 31;
    const int w    = t >> 5;
    const int wm   = (w & 3) * 32;   // warp M offset in tile
    const int wn   = (w >> 2) * 64;  // warp N offset in tile

    const int n0 = blockIdx.x * 128;
    const int m0 = blockIdx.y * 128;

    // loader thread-fixed coordinates
    const int am = t >> 2, ac = t & 3;
    const int aoff0 = am * 4        + (ac ^ ((am >> 1) & 3));
    const int aoff1 = (am + 64) * 4 + (ac ^ ((am >> 1) & 3));
    const int bk = t >> 4, bcn = t & 15;
    const int boff0 = bk * 16        + (bcn ^ (bk & 7));
    const int boff1 = (bk + 16) * 16 + (bcn ^ (bk & 7));

    const uint32_t asb = smem_u32(&As4[0][0]);
    const uint32_t bsb = smem_u32(&Bs4[0][0]);

    int tot = 0;
#pragma unroll
    for (int s = 0; s < 2; s++) if (s < SL.n) tot += SL.s[s].kchunks;

    float d[2][8][4];
#pragma unroll
    for (int i = 0; i < 2; i++)
#pragma unroll
        for (int j = 0; j < 8; j++)
#pragma unroll
            for (int q = 0; q < 4; q++) d[i][j][q] = 0.f;

    int ls = 0, lc = 0;   // next chunk to load: segment / chunk-in-segment

    auto issue = [&](int buf) {
        const Seg sg = SL.s[ls];
        const __half* Ap = sg.A + (size_t)(m0 + am) * sg.lda + lc * 32 + ac * 8;
        CP16(asb + (uint32_t)(buf * 512 + aoff0) * 16, Ap);
        CP16(asb + (uint32_t)(buf * 512 + aoff1) * 16, Ap + (size_t)64 * sg.lda);
        const __half* Bp = sg.B + (size_t)(lc * 32 + bk) * N + n0 + bcn * 8;
        CP16(bsb + (uint32_t)(buf * 512 + boff0) * 16, Bp);
        CP16(bsb + (uint32_t)(buf * 512 + boff1) * 16, Bp + (size_t)16 * N);
        asm volatile("cp.async.commit_group;\n");
        if (++lc == sg.kchunks) { lc = 0; ++ls; }
    };

    issue(0);
    int issued = 1;

    for (int i = 0; i < tot; i++) {
        const int buf = i & 1;
        if (issued < tot) { issue(issued & 1); issued++; cp_wait<1>(); }
        else              { cp_wait<0>(); }
        __syncthreads();

#pragma unroll
        for (int kk = 0; kk < 2; kk++) {
            // A fragments: 2 m16 tiles
            uint32_t a[2][4];
#pragma unroll
            for (int mi = 0; mi < 2; mi++) {
                const int mrow = wm + mi * 16 + (lane & 15);
                const int c    = kk * 2 + (lane >> 4);
                const int phys = mrow * 4 + (c ^ ((mrow >> 1) & 3));
                ldsm_x4(a[mi], asb + (uint32_t)(buf * 512 + phys) * 16);
            }
            // B fragments (4 groups of n16) + MMAs
#pragma unroll
            for (int j = 0; j < 4; j++) {
                uint32_t bb[4];
                const int krow = kk * 16 + (lane & 15);
                const int cn   = (wn >> 3) + j * 2 + (lane >> 4);
                const int phys = krow * 16 + (cn ^ (krow & 7));
                ldsm_x4_t(bb, bsb + (uint32_t)(buf * 512 + phys) * 16);
#pragma unroll
                for (int mi = 0; mi < 2; mi++) {
                    mma16816(d[mi][2 * j],     a[mi], bb[0], bb[1]);
                    mma16816(d[mi][2 * j + 1], a[mi], bb[2], bb[3]);
                }
            }
        }
        __syncthreads();
    }

    // ---- epilogue: bias + leaky-relu + fp16 store ----
#pragma unroll
    for (int mi = 0; mi < 2; mi++) {
#pragma unroll
        for (int j = 0; j < 8; j++) {
            const int col  = n0 + wn + j * 8 + (lane & 3) * 2;
            const float b0 = bias[col], b1 = bias[col + 1];
#pragma unroll
            for (int rh = 0; rh < 2; rh++) {
                const int row = m0 + wm + mi * 16 + (lane >> 2) + rh * 8;
                float v0 = d[mi][j][2 * rh]     + b0;
                float v1 = d[mi][j][2 * rh + 1] + b1;
                v0 = (v0 > 0.f) ? v0 : 0.02f * v0;
                v1 = (v1 > 0.f) ? v1 : 0.02f * v1;
                *reinterpret_cast<__half2*>(out + (size_t)row * N + col) =
                    __halves2half2(__float2half(v0), __float2half(v1));
            }
        }
    }
}

// ---------------------------------------------------------------------------
// Final layer: out[m] = h5[m,:] . W6 + b6   (128 -> 1)
// ---------------------------------------------------------------------------
__global__ void final_kernel(const __half* __restrict__ h5,
                             const float* __restrict__ W6,
                             const float* __restrict__ b6,
                             float* __restrict__ out)
{
    const int warp = threadIdx.x >> 5;
    const int lane = threadIdx.x & 31;
    const int m = blockIdx.x * 8 + warp;

    float s = 0.f;
#pragma unroll
    for (int j = 0; j < 4; j++) {
        const int c = 4 * lane + j;
        s = fmaf(__half2float(h5[(size_t)m * 128 + c]), W6[c], s);
    }
#pragma unroll
    for (int o = 16; o > 0; o >>= 1)
        s += __shfl_xor_sync(0xffffffffu, s, o);
    if (lane == 0) out[m] = s + b6[0];
}

// ---------------------------------------------------------------------------
// Launch
// ---------------------------------------------------------------------------
extern "C" void kernel_launch(void* const* d_in, const int* in_sizes, int n_in,
                              void* d_out, int out_size)
{
    (void)in_sizes; (void)n_in; (void)out_size;

    const int*   indices = (const int*)  d_in[0];
    const float* qp      = (const float*)d_in[1];
    const float* cpos    = (const float*)d_in[2];
    const float* codes   = (const float*)d_in[3];
    const float* W1 = (const float*)d_in[4];  const float* b1 = (const float*)d_in[5];
    const float* W2 = (const float*)d_in[6];  const float* b2 = (const float*)d_in[7];
    const float* W3 = (const float*)d_in[8];  const float* b3 = (const float*)d_in[9];
    const float* W4 = (const float*)d_in[10]; const float* b4 = (const float*)d_in[11];
    const float* W5 = (const float*)d_in[12]; const float* b5 = (const float*)d_in[13];
    const float* W6 = (const float*)d_in[14]; const float* b6 = (const float*)d_in[15];
    float* out = (float*)d_out;

    __half *x, *h1, *h2, *h3, *h4, *h5, *wq;
    cudaGetSymbolAddress((void**)&x,  g_x);
    cudaGetSymbolAddress((void**)&h1, g_h1); cudaGetSymbolAddress((void**)&h2, g_h2);
    cudaGetSymbolAddress((void**)&h3, g_h3); cudaGetSymbolAddress((void**)&h4, g_h4);
    cudaGetSymbolAddress((void**)&h5, g_h5); cudaGetSymbolAddress((void**)&wq, g_wq);

    // weight plane offsets (single fp16 plane per part)
    size_t off = 0;
    auto take = [&](size_t nelem) { __half* p = wq + off; off += nelem; return p; };
    __half* w1x = take((size_t)XK * 2048);
    __half* w2h = take((size_t)2048 * 1024);
    __half* w2x = take((size_t)XK * 1024);
    __half* w3h = take((size_t)1024 * 512);
    __half* w3x = take((size_t)XK * 512);
    __half* w4h = take((size_t)512 * 256);
    __half* w4x = take((size_t)XK * 256);
    __half* w5h = take((size_t)256 * 128);
    __half* w5x = take((size_t)XK * 128);

    // weight prep (fp32 -> fp16, x-part padded to 160 rows)
    auto prep = [&](const float* W, int K1, int N, __half* hh, __half* xh) {
        int tot = (K1 + XK) * N;
        prep_w<<<(tot + 255) / 256, 256>>>(W, K1, N, hh, xh);
    };
    prep(W1, 0,    2048, w1x, w1x);
    prep(W2, 2048, 1024, w2h, w2x);
    prep(W3, 1024, 512,  w3h, w3x);
    prep(W4, 512,  256,  w4h, w4x);
    prep(W5, 256,  128,  w5h, w5x);

    // stage 1
    const int s1_smem = NK * ND * (int)sizeof(float) + 8 * NK * (int)sizeof(float);
    cudaFuncSetAttribute(stage1_kernel, cudaFuncAttributeMaxDynamicSharedMemorySize, s1_smem);
    stage1_kernel<<<dim3(NB, NP / PPB), 256, s1_smem>>>(indices, qp, cpos, codes);

    // layers:  act( h @ Wh + x @ Wx + b ) ; all activations single fp16 plane
    auto run = [&](int N, const float* bias,
                   __half* Ah, int K1, __half* Wh, __half* Wx, __half* Oh) {
        SegList SL;
        int n = 0;
        if (K1 > 0) SL.s[n++] = { Ah, Wh, K1, K1 >> 5 };
        SL.s[n++] = { x, Wx, XK, XK >> 5 };
        SL.n = n;
        mma_gemm<<<dim3(N / 128, NM / 128), 256>>>(SL, bias, N, Oh);
    };

    run(2048, b1, nullptr, 0,    nullptr, w1x, h1);
    run(1024, b2, h1, 2048, w2h, w2x, h2);
    run(512,  b3, h2, 1024, w3h, w3x, h3);
    run(256,  b4, h3, 512,  w4h, w4x, h4);
    run(128,  b5, h4, 256,  w5h, w5x, h5);

    // Final 128 -> 1 dot
    final_kernel<<<NM / 8, 256>>>(h5, W6, b6, out);
}

// round 15
// speedup vs baseline: 1.2537x; 1.0115x over previous
#include <cuda_runtime.h>
#include <cuda_fp16.h>
#include <stdint.h>

// ---------------------------------------------------------------------------
// Problem constants
// ---------------------------------------------------------------------------
#define NB   8
#define NP   8192
#define NM   (NB * NP)          // 65536 rows
#define NK   128                // codes per record
#define ND   128                // code dim
#define XK   160                // padded x K-dim (131 valid, rest zero) — mult of 32
#define PPB  128                // stage-1 points per block

// ---------------------------------------------------------------------------
// Scratch: single fp16 planes for x and h activations; fp16 weights.
// ---------------------------------------------------------------------------
__device__ __half g_x [(size_t)NM * XK];
__device__ __half g_h1[(size_t)NM * 2048];
__device__ __half g_h2[(size_t)NM * 1024];
__device__ __half g_h3[(size_t)NM * 512];
__device__ __half g_h4[(size_t)NM * 256];
__device__ __half g_h5[(size_t)NM * 128];
// fp16 weights (single plane): sum of (K1+160)*N over 5 layers = 3,420,160
__device__ __half g_wq[3500000];

// ---------------------------------------------------------------------------
// Helpers
// ---------------------------------------------------------------------------
__device__ __forceinline__ uint32_t smem_u32(const void* p)
{
    return (uint32_t)__cvta_generic_to_shared(p);
}

template<int Ngrp> __device__ __forceinline__ void cp_wait()
{
    asm volatile("cp.async.wait_group %0;\n" :: "n"(Ngrp));
}

#define CP16(dst_u32, src_ptr) \
    asm volatile("cp.async.cg.shared.global [%0], [%1], 16;\n" :: "r"(dst_u32), "l"(src_ptr))

__device__ __forceinline__ void ldsm_x4(uint32_t* r, uint32_t addr)
{
    asm volatile("ldmatrix.sync.aligned.m8n8.x4.shared.b16 {%0,%1,%2,%3}, [%4];\n"
                 : "=r"(r[0]), "=r"(r[1]), "=r"(r[2]), "=r"(r[3]) : "r"(addr));
}

__device__ __forceinline__ void ldsm_x4_t(uint32_t* r, uint32_t addr)
{
    asm volatile("ldmatrix.sync.aligned.m8n8.x4.trans.shared.b16 {%0,%1,%2,%3}, [%4];\n"
                 : "=r"(r[0]), "=r"(r[1]), "=r"(r[2]), "=r"(r[3]) : "r"(addr));
}

__device__ __forceinline__ void mma16816(float* d, const uint32_t* a, uint32_t b0, uint32_t b1)
{
    asm volatile(
        "mma.sync.aligned.m16n8k16.row.col.f32.f16.f16.f32 "
        "{%0,%1,%2,%3}, {%4,%5,%6,%7}, {%8,%9}, {%0,%1,%2,%3};\n"
        : "+f"(d[0]), "+f"(d[1]), "+f"(d[2]), "+f"(d[3])
        : "r"(a[0]), "r"(a[1]), "r"(a[2]), "r"(a[3]), "r"(b0), "r"(b1));
}

// ---------------------------------------------------------------------------
// Stage 1: inverse-square-distance weighted code interpolation -> x plane
// x[m, 0:128] = weighted codes, x[m,128:131] = query point, 131..159 = 0
// ---------------------------------------------------------------------------
__global__ void stage1_kernel(const int* __restrict__ indices,
                              const float* __restrict__ qp,
                              const float* __restrict__ codes_pos,
                              const float* __restrict__ codes)
{
    extern __shared__ float smem[];
    float4* bc4 = reinterpret_cast<float4*>(smem);   // [128 codes][32 float4]
    float*  ws  = smem + NK * ND;                    // [8 warps][128] weights

    const int b   = blockIdx.x;
    const int rec = indices[b];

    const float4* csrc = reinterpret_cast<const float4*>(codes + (size_t)rec * NK * ND);
    for (int i = threadIdx.x; i < NK * (ND / 4); i += blockDim.x)
        bc4[i] = csrc[i];
    __syncthreads();

    const int warp = threadIdx.x >> 5;
    const int lane = threadIdx.x & 31;

    const float* pbase = codes_pos + (size_t)rec * NK * 3;
    float cpx[4], cpy[4], cpz[4];
#pragma unroll
    for (int t = 0; t < 4; t++) {
        int k = lane + 32 * t;
        cpx[t] = pbase[k * 3 + 0];
        cpy[t] = pbase[k * 3 + 1];
        cpz[t] = pbase[k * 3 + 2];
    }

    float* wsw = ws + warp * NK;
    const int p0 = blockIdx.y * PPB;

    for (int pi = warp; pi < PPB; pi += 8) {
        const int m = b * NP + p0 + pi;
        const float qx = qp[(size_t)m * 3 + 0];
        const float qy = qp[(size_t)m * 3 + 1];
        const float qz = qp[(size_t)m * 3 + 2];

        float wsum = 0.f;
#pragma unroll
        for (int t = 0; t < 4; t++) {
            float dx = qx - cpx[t], dy = qy - cpy[t], dz = qz - cpz[t];
            float sq = dx * dx + dy * dy + dz * dz + 1e-16f;
            float w  = 1.0f / sq;
            wsw[lane + 32 * t] = w;
            wsum += w;
        }
        __syncwarp();
#pragma unroll
        for (int o = 16; o > 0; o >>= 1)
            wsum += __shfl_xor_sync(0xffffffffu, wsum, o);

        float4 acc = make_float4(0.f, 0.f, 0.f, 0.f);
#pragma unroll 4
        for (int k = 0; k < NK; k++) {
            const float  w = wsw[k];
            const float4 c = bc4[k * 32 + lane];
            acc.x = fmaf(w, c.x, acc.x);
            acc.y = fmaf(w, c.y, acc.y);
            acc.z = fmaf(w, c.z, acc.z);
            acc.w = fmaf(w, c.w, acc.w);
        }
        const float inv = 1.0f / wsum;

        __half* xh = g_x + (size_t)m * XK;
        float v[4] = { acc.x * inv, acc.y * inv, acc.z * inv, acc.w * inv };
#pragma unroll
        for (int j = 0; j < 4; j++)
            xh[4 * lane + j] = __float2half(v[j]);

        // tail cols 128..159: query point then zeros (one col per lane)
        {
            const int c = 128 + lane;
            float q = 0.f;
            if (lane == 0) q = qx; else if (lane == 1) q = qy; else if (lane == 2) q = qz;
            xh[c] = __float2half(q);
        }
        __syncwarp();
    }
}

// ---------------------------------------------------------------------------
// Weight prep: fp32 W[K1+131, N] -> single fp16 plane, x-part padded to 160 rows
// Layout preserved: hh[k, n] (K1 x N), xh[k2, n] (XK x N)
// ---------------------------------------------------------------------------
__global__ void prep_w(const float* __restrict__ W, int K1, int N,
                       __half* __restrict__ hh, __half* __restrict__ xh)
{
    const int idx = blockIdx.x * blockDim.x + threadIdx.x;
    const int tot = (K1 + XK) * N;
    if (idx >= tot) return;
    const int r = idx / N, n = idx - r * N;
    if (r < K1) {
        hh[(size_t)r * N + n] = __float2half(W[(size_t)r * N + n]);
    } else {
        const int r2 = r - K1;
        float v = (r2 < 131) ? W[(size_t)(K1 + r2) * N + n] : 0.f;
        xh[(size_t)r2 * N + n] = __float2half(v);
    }
}

// ---------------------------------------------------------------------------
// Segmented fp16 tensor-core GEMM with fused bias + leaky-relu + fp16 store.
//   Out[m,n] = act( h @ Wh + x @ Wx + bias )   (skip-concat via segments)
// CTA 128x128, 8 warps (32x64 each), K-chunks of 32.
// THREE-stage cp.async pipeline (R14 structure + 1 extra buffer; layout,
// swizzle, loader mapping and inner loop byte-identical to the proven kernel).
// ---------------------------------------------------------------------------
struct Seg { const __half* A; const __half* B; int lda; int kchunks; };
struct SegList { Seg s[2]; int n; };

__global__ __launch_bounds__(256, 2)
void mma_gemm(SegList SL, const float* __restrict__ bias, int N,
              __half* __restrict__ out)
{
    __shared__ uint4 As4[3][512];   // [buf][m(128) x chunk(4)] xor-swizzled
    __shared__ uint4 Bs4[3][512];   // [buf][k(32) x chunk(16)] xor-swizzled

    const int t    = threadIdx.x;
    const int lane = t & 31;
    const int w    = t >> 5;
    const int wm   = (w & 3) * 32;   // warp M offset in tile
    const int wn   = (w >> 2) * 64;  // warp N offset in tile

    const int n0 = blockIdx.x * 128;
    const int m0 = blockIdx.y * 128;

    // loader thread-fixed coordinates
    const int am = t >> 2, ac = t & 3;
    const int aoff0 = am * 4        + (ac ^ ((am >> 1) & 3));
    const int aoff1 = (am + 64) * 4 + (ac ^ ((am >> 1) & 3));
    const int bk = t >> 4, bcn = t & 15;
    const int boff0 = bk * 16        + (bcn ^ (bk & 7));
    const int boff1 = (bk + 16) * 16 + (bcn ^ (bk & 7));

    const uint32_t asb = smem_u32(&As4[0][0]);
    const uint32_t bsb = smem_u32(&Bs4[0][0]);

    int tot = 0;
#pragma unroll
    for (int s = 0; s < 2; s++) if (s < SL.n) tot += SL.s[s].kchunks;

    float d[2][8][4];
#pragma unroll
    for (int i = 0; i < 2; i++)
#pragma unroll
        for (int j = 0; j < 8; j++)
#pragma unroll
            for (int q = 0; q < 4; q++) d[i][j][q] = 0.f;

    int ls = 0, lc = 0;   // next chunk to load: segment / chunk-in-segment

    auto issue = [&](int buf) {
        const Seg sg = SL.s[ls];
        const __half* Ap = sg.A + (size_t)(m0 + am) * sg.lda + lc * 32 + ac * 8;
        CP16(asb + (uint32_t)(buf * 512 + aoff0) * 16, Ap);
        CP16(asb + (uint32_t)(buf * 512 + aoff1) * 16, Ap + (size_t)64 * sg.lda);
        const __half* Bp = sg.B + (size_t)(lc * 32 + bk) * N + n0 + bcn * 8;
        CP16(bsb + (uint32_t)(buf * 512 + boff0) * 16, Bp);
        CP16(bsb + (uint32_t)(buf * 512 + boff1) * 16, Bp + (size_t)16 * N);
        asm volatile("cp.async.commit_group;\n");
        if (++lc == sg.kchunks) { lc = 0; ++ls; }
    };

    // prologue: fill 2 of 3 stages (all layers have tot >= 5)
    issue(0);
    issue(1);
    int issued = 2;
    int ibuf = 2;   // next buffer to fill

    int buf = 0;    // buffer being consumed this iteration
    for (int i = 0; i < tot; i++) {
        if (issued < tot) {
            issue(ibuf);
            issued++;
            if (++ibuf == 3) ibuf = 0;
            cp_wait<2>();
        } else {
            cp_wait<0>();
        }
        __syncthreads();

#pragma unroll
        for (int kk = 0; kk < 2; kk++) {
            // A fragments: 2 m16 tiles
            uint32_t a[2][4];
#pragma unroll
            for (int mi = 0; mi < 2; mi++) {
                const int mrow = wm + mi * 16 + (lane & 15);
                const int c    = kk * 2 + (lane >> 4);
                const int phys = mrow * 4 + (c ^ ((mrow >> 1) & 3));
                ldsm_x4(a[mi], asb + (uint32_t)(buf * 512 + phys) * 16);
            }
            // B fragments (4 groups of n16) + MMAs
#pragma unroll
            for (int j = 0; j < 4; j++) {
                uint32_t bb[4];
                const int krow = kk * 16 + (lane & 15);
                const int cn   = (wn >> 3) + j * 2 + (lane >> 4);
                const int phys = krow * 16 + (cn ^ (krow & 7));
                ldsm_x4_t(bb, bsb + (uint32_t)(buf * 512 + phys) * 16);
#pragma unroll
                for (int mi = 0; mi < 2; mi++) {
                    mma16816(d[mi][2 * j],     a[mi], bb[0], bb[1]);
                    mma16816(d[mi][2 * j + 1], a[mi], bb[2], bb[3]);
                }
            }
        }
        __syncthreads();
        if (++buf == 3) buf = 0;
    }

    // ---- epilogue: bias + leaky-relu + fp16 store ----
#pragma unroll
    for (int mi = 0; mi < 2; mi++) {
#pragma unroll
        for (int j = 0; j < 8; j++) {
            const int col  = n0 + wn + j * 8 + (lane & 3) * 2;
            const float b0 = bias[col], b1 = bias[col + 1];
#pragma unroll
            for (int rh = 0; rh < 2; rh++) {
                const int row = m0 + wm + mi * 16 + (lane >> 2) + rh * 8;
                float v0 = d[mi][j][2 * rh]     + b0;
                float v1 = d[mi][j][2 * rh + 1] + b1;
                v0 = (v0 > 0.f) ? v0 : 0.02f * v0;
                v1 = (v1 > 0.f) ? v1 : 0.02f * v1;
                *reinterpret_cast<__half2*>(out + (size_t)row * N + col) =
                    __halves2half2(__float2half(v0), __float2half(v1));
            }
        }
    }
}

// ---------------------------------------------------------------------------
// Final layer: out[m] = h5[m,:] . W6 + b6   (128 -> 1)
// ---------------------------------------------------------------------------
__global__ void final_kernel(const __half* __restrict__ h5,
                             const float* __restrict__ W6,
                             const float* __restrict__ b6,
                             float* __restrict__ out)
{
    const int warp = threadIdx.x >> 5;
    const int lane = threadIdx.x & 31;
    const int m = blockIdx.x * 8 + warp;

    float s = 0.f;
#pragma unroll
    for (int j = 0; j < 4; j++) {
        const int c = 4 * lane + j;
        s = fmaf(__half2float(h5[(size_t)m * 128 + c]), W6[c], s);
    }
#pragma unroll
    for (int o = 16; o > 0; o >>= 1)
        s += __shfl_xor_sync(0xffffffffu, s, o);
    if (lane == 0) out[m] = s + b6[0];
}

// ---------------------------------------------------------------------------
// Launch
// ---------------------------------------------------------------------------
extern "C" void kernel_launch(void* const* d_in, const int* in_sizes, int n_in,
                              void* d_out, int out_size)
{
    (void)in_sizes; (void)n_in; (void)out_size;

    const int*   indices = (const int*)  d_in[0];
    const float* qp      = (const float*)d_in[1];
    const float* cpos    = (const float*)d_in[2];
    const float* codes   = (const float*)d_in[3];
    const float* W1 = (const float*)d_in[4];  const float* b1 = (const float*)d_in[5];
    const float* W2 = (const float*)d_in[6];  const float* b2 = (const float*)d_in[7];
    const float* W3 = (const float*)d_in[8];  const float* b3 = (const float*)d_in[9];
    const float* W4 = (const float*)d_in[10]; const float* b4 = (const float*)d_in[11];
    const float* W5 = (const float*)d_in[12]; const float* b5 = (const float*)d_in[13];
    const float* W6 = (const float*)d_in[14]; const float* b6 = (const float*)d_in[15];
    float* out = (float*)d_out;

    __half *x, *h1, *h2, *h3, *h4, *h5, *wq;
    cudaGetSymbolAddress((void**)&x,  g_x);
    cudaGetSymbolAddress((void**)&h1, g_h1); cudaGetSymbolAddress((void**)&h2, g_h2);
    cudaGetSymbolAddress((void**)&h3, g_h3); cudaGetSymbolAddress((void**)&h4, g_h4);
    cudaGetSymbolAddress((void**)&h5, g_h5); cudaGetSymbolAddress((void**)&wq, g_wq);

    // weight plane offsets (single fp16 plane per part)
    size_t off = 0;
    auto take = [&](size_t nelem) { __half* p = wq + off; off += nelem; return p; };
    __half* w1x = take((size_t)XK * 2048);
    __half* w2h = take((size_t)2048 * 1024);
    __half* w2x = take((size_t)XK * 1024);
    __half* w3h = take((size_t)1024 * 512);
    __half* w3x = take((size_t)XK * 512);
    __half* w4h = take((size_t)512 * 256);
    __half* w4x = take((size_t)XK * 256);
    __half* w5h = take((size_t)256 * 128);
    __half* w5x = take((size_t)XK * 128);

    // weight prep (fp32 -> fp16, x-part padded to 160 rows)
    auto prep = [&](const float* W, int K1, int N, __half* hh, __half* xh) {
        int tot = (K1 + XK) * N;
        prep_w<<<(tot + 255) / 256, 256>>>(W, K1, N, hh, xh);
    };
    prep(W1, 0,    2048, w1x, w1x);
    prep(W2, 2048, 1024, w2h, w2x);
    prep(W3, 1024, 512,  w3h, w3x);
    prep(W4, 512,  256,  w4h, w4x);
    prep(W5, 256,  128,  w5h, w5x);

    // stage 1
    const int s1_smem = NK * ND * (int)sizeof(float) + 8 * NK * (int)sizeof(float);
    cudaFuncSetAttribute(stage1_kernel, cudaFuncAttributeMaxDynamicSharedMemorySize, s1_smem);
    stage1_kernel<<<dim3(NB, NP / PPB), 256, s1_smem>>>(indices, qp, cpos, codes);

    // layers:  act( h @ Wh + x @ Wx + b ) ; all activations single fp16 plane
    auto run = [&](int N, const float* bias,
                   __half* Ah, int K1, __half* Wh, __half* Wx, __half* Oh) {
        SegList SL;
        int n = 0;
        if (K1 > 0) SL.s[n++] = { Ah, Wh, K1, K1 >> 5 };
        SL.s[n++] = { x, Wx, XK, XK >> 5 };
        SL.n = n;
        mma_gemm<<<dim3(N / 128, NM / 128), 256>>>(SL, bias, N, Oh);
    };

    run(2048, b1, nullptr, 0,    nullptr, w1x, h1);
    run(1024, b2, h1, 2048, w2h, w2x, h2);
    run(512,  b3, h2, 1024, w3h, w3x, h3);
    run(256,  b4, h3, 512,  w4h, w4x, h4);
    run(128,  b5, h4, 256,  w5h, w5x, h5);

    // Final 128 -> 1 dot
    final_kernel<<<NM / 8, 256>>>(h5, W6, b6, out);
}

// round 16
// speedup vs baseline: 1.2844x; 1.0245x over previous
#include <cuda_runtime.h>
#include <cuda_fp16.h>
#include <stdint.h>

// ---------------------------------------------------------------------------
// Problem constants
// ---------------------------------------------------------------------------
#define NB   8
#define NP   8192
#define NM   (NB * NP)          // 65536 rows
#define NK   128                // codes per record
#define ND   128                // code dim
#define XK   160                // padded x K-dim (131 valid, rest zero) — mult of 32
#define PPB  128                // stage-1 points per block

// ---------------------------------------------------------------------------
// Scratch: single fp16 planes for x and h activations; fp16 weights.
// ---------------------------------------------------------------------------
__device__ __half g_x [(size_t)NM * XK];
__device__ __half g_h1[(size_t)NM * 2048];
__device__ __half g_h2[(size_t)NM * 1024];
__device__ __half g_h3[(size_t)NM * 512];
__device__ __half g_h4[(size_t)NM * 256];
__device__ __half g_h5[(size_t)NM * 128];
// fp16 weights (single plane): sum of (K1+160)*N over 5 layers = 3,420,160
__device__ __half g_wq[3500000];

// ---------------------------------------------------------------------------
// Helpers
// ---------------------------------------------------------------------------
__device__ __forceinline__ uint32_t smem_u32(const void* p)
{
    return (uint32_t)__cvta_generic_to_shared(p);
}

template<int Ngrp> __device__ __forceinline__ void cp_wait()
{
    asm volatile("cp.async.wait_group %0;\n" :: "n"(Ngrp));
}

#define CP16(dst_u32, src_ptr) \
    asm volatile("cp.async.cg.shared.global [%0], [%1], 16;\n" :: "r"(dst_u32), "l"(src_ptr))

__device__ __forceinline__ void ldsm_x4(uint32_t* r, uint32_t addr)
{
    asm volatile("ldmatrix.sync.aligned.m8n8.x4.shared.b16 {%0,%1,%2,%3}, [%4];\n"
                 : "=r"(r[0]), "=r"(r[1]), "=r"(r[2]), "=r"(r[3]) : "r"(addr));
}

__device__ __forceinline__ void ldsm_x4_t(uint32_t* r, uint32_t addr)
{
    asm volatile("ldmatrix.sync.aligned.m8n8.x4.trans.shared.b16 {%0,%1,%2,%3}, [%4];\n"
                 : "=r"(r[0]), "=r"(r[1]), "=r"(r[2]), "=r"(r[3]) : "r"(addr));
}

__device__ __forceinline__ void mma16816(float* d, const uint32_t* a, uint32_t b0, uint32_t b1)
{
    asm volatile(
        "mma.sync.aligned.m16n8k16.row.col.f32.f16.f16.f32 "
        "{%0,%1,%2,%3}, {%4,%5,%6,%7}, {%8,%9}, {%0,%1,%2,%3};\n"
        : "+f"(d[0]), "+f"(d[1]), "+f"(d[2]), "+f"(d[3])
        : "r"(a[0]), "r"(a[1]), "r"(a[2]), "r"(a[3]), "r"(b0), "r"(b1));
}

// ---------------------------------------------------------------------------
// Stage 1: inverse-square-distance weighted code interpolation -> x plane
// x[m, 0:128] = weighted codes, x[m,128:131] = query point, 131..159 = 0
// ---------------------------------------------------------------------------
__global__ void stage1_kernel(const int* __restrict__ indices,
                              const float* __restrict__ qp,
                              const float* __restrict__ codes_pos,
                              const float* __restrict__ codes)
{
    extern __shared__ float smem[];
    float4* bc4 = reinterpret_cast<float4*>(smem);   // [128 codes][32 float4]
    float*  ws  = smem + NK * ND;                    // [8 warps][128] weights

    const int b   = blockIdx.x;
    const int rec = indices[b];

    const float4* csrc = reinterpret_cast<const float4*>(codes + (size_t)rec * NK * ND);
    for (int i = threadIdx.x; i < NK * (ND / 4); i += blockDim.x)
        bc4[i] = csrc[i];
    __syncthreads();

    const int warp = threadIdx.x >> 5;
    const int lane = threadIdx.x & 31;

    const float* pbase = codes_pos + (size_t)rec * NK * 3;
    float cpx[4], cpy[4], cpz[4];
#pragma unroll
    for (int t = 0; t < 4; t++) {
        int k = lane + 32 * t;
        cpx[t] = pbase[k * 3 + 0];
        cpy[t] = pbase[k * 3 + 1];
        cpz[t] = pbase[k * 3 + 2];
    }

    float* wsw = ws + warp * NK;
    const int p0 = blockIdx.y * PPB;

    for (int pi = warp; pi < PPB; pi += 8) {
        const int m = b * NP + p0 + pi;
        const float qx = qp[(size_t)m * 3 + 0];
        const float qy = qp[(size_t)m * 3 + 1];
        const float qz = qp[(size_t)m * 3 + 2];

        float wsum = 0.f;
#pragma unroll
        for (int t = 0; t < 4; t++) {
            float dx = qx - cpx[t], dy = qy - cpy[t], dz = qz - cpz[t];
            float sq = dx * dx + dy * dy + dz * dz + 1e-16f;
            float w  = 1.0f / sq;
            wsw[lane + 32 * t] = w;
            wsum += w;
        }
        __syncwarp();
#pragma unroll
        for (int o = 16; o > 0; o >>= 1)
            wsum += __shfl_xor_sync(0xffffffffu, wsum, o);

        float4 acc = make_float4(0.f, 0.f, 0.f, 0.f);
#pragma unroll 4
        for (int k = 0; k < NK; k++) {
            const float  w = wsw[k];
            const float4 c = bc4[k * 32 + lane];
            acc.x = fmaf(w, c.x, acc.x);
            acc.y = fmaf(w, c.y, acc.y);
            acc.z = fmaf(w, c.z, acc.z);
            acc.w = fmaf(w, c.w, acc.w);
        }
        const float inv = 1.0f / wsum;

        __half* xh = g_x + (size_t)m * XK;
        float v[4] = { acc.x * inv, acc.y * inv, acc.z * inv, acc.w * inv };
#pragma unroll
        for (int j = 0; j < 4; j++)
            xh[4 * lane + j] = __float2half(v[j]);

        // tail cols 128..159: query point then zeros (one col per lane)
        {
            const int c = 128 + lane;
            float q = 0.f;
            if (lane == 0) q = qx; else if (lane == 1) q = qy; else if (lane == 2) q = qz;
            xh[c] = __float2half(q);
        }
        __syncwarp();
    }
}

// ---------------------------------------------------------------------------
// Weight prep (vectorized 8-wide): fp32 W[K1+131, N] -> single fp16 plane,
// x-part padded to 160 rows. Same values as scalar version, 8 elems/thread.
// ---------------------------------------------------------------------------
__global__ void prep_w(const float* __restrict__ W, int K1, int N,
                       __half* __restrict__ hh, __half* __restrict__ xh)
{
    const int N8  = N >> 3;
    const int idx = blockIdx.x * blockDim.x + threadIdx.x;
    const int tot = (K1 + XK) * N8;
    if (idx >= tot) return;
    const int r  = idx / N8;
    const int n0 = (idx - r * N8) << 3;

    float f[8];
    __half* dst;
    if (r < K1) {
        const float4 a = *reinterpret_cast<const float4*>(W + (size_t)r * N + n0);
        const float4 b = *reinterpret_cast<const float4*>(W + (size_t)r * N + n0 + 4);
        f[0]=a.x; f[1]=a.y; f[2]=a.z; f[3]=a.w;
        f[4]=b.x; f[5]=b.y; f[6]=b.z; f[7]=b.w;
        dst = hh + (size_t)r * N + n0;
    } else {
        const int r2 = r - K1;
        if (r2 < 131) {
            const float4 a = *reinterpret_cast<const float4*>(W + (size_t)(K1 + r2) * N + n0);
            const float4 b = *reinterpret_cast<const float4*>(W + (size_t)(K1 + r2) * N + n0 + 4);
            f[0]=a.x; f[1]=a.y; f[2]=a.z; f[3]=a.w;
            f[4]=b.x; f[5]=b.y; f[6]=b.z; f[7]=b.w;
        } else {
#pragma unroll
            for (int j = 0; j < 8; j++) f[j] = 0.f;
        }
        dst = xh + (size_t)r2 * N + n0;
    }

    __half2 h2[4];
#pragma unroll
    for (int j = 0; j < 4; j++)
        h2[j] = __halves2half2(__float2half(f[2 * j]), __float2half(f[2 * j + 1]));
    *reinterpret_cast<uint4*>(dst) = *reinterpret_cast<const uint4*>(h2);
}

// ---------------------------------------------------------------------------
// Segmented fp16 tensor-core GEMM with fused bias + leaky-relu + fp16 store.
//   Out[m,n] = act( h @ Wh + x @ Wx + bias )   (skip-concat via segments)
// CTA 128x128, 8 warps (32x64 each), K-chunks of 32, 3-stage ring.
// SINGLE __syncthreads per iteration (cutlass multistage schedule):
//   { wait_group(1) ; sync ; issue into buffer consumed 2 iters ago
//     (or empty commit_group in the tail) ; compute }
// Layout, swizzle, loaders and inner compute identical to the proven kernel.
// ---------------------------------------------------------------------------
struct Seg { const __half* A; const __half* B; int lda; int kchunks; };
struct SegList { Seg s[2]; int n; };

__global__ __launch_bounds__(256, 2)
void mma_gemm(SegList SL, const float* __restrict__ bias, int N,
              __half* __restrict__ out)
{
    __shared__ uint4 As4[3][512];   // [buf][m(128) x chunk(4)] xor-swizzled
    __shared__ uint4 Bs4[3][512];   // [buf][k(32) x chunk(16)] xor-swizzled

    const int t    = threadIdx.x;
    const int lane = t & 31;
    const int w    = t >> 5;
    const int wm   = (w & 3) * 32;   // warp M offset in tile
    const int wn   = (w >> 2) * 64;  // warp N offset in tile

    const int n0 = blockIdx.x * 128;
    const int m0 = blockIdx.y * 128;

    // loader thread-fixed coordinates
    const int am = t >> 2, ac = t & 3;
    const int aoff0 = am * 4        + (ac ^ ((am >> 1) & 3));
    const int aoff1 = (am + 64) * 4 + (ac ^ ((am >> 1) & 3));
    const int bk = t >> 4, bcn = t & 15;
    const int boff0 = bk * 16        + (bcn ^ (bk & 7));
    const int boff1 = (bk + 16) * 16 + (bcn ^ (bk & 7));

    const uint32_t asb = smem_u32(&As4[0][0]);
    const uint32_t bsb = smem_u32(&Bs4[0][0]);

    int tot = 0;
#pragma unroll
    for (int s = 0; s < 2; s++) if (s < SL.n) tot += SL.s[s].kchunks;

    float d[2][8][4];
#pragma unroll
    for (int i = 0; i < 2; i++)
#pragma unroll
        for (int j = 0; j < 8; j++)
#pragma unroll
            for (int q = 0; q < 4; q++) d[i][j][q] = 0.f;

    int ls = 0, lc = 0;   // next chunk to load: segment / chunk-in-segment

    auto issue = [&](int buf) {
        const Seg sg = SL.s[ls];
        const __half* Ap = sg.A + (size_t)(m0 + am) * sg.lda + lc * 32 + ac * 8;
        CP16(asb + (uint32_t)(buf * 512 + aoff0) * 16, Ap);
        CP16(asb + (uint32_t)(buf * 512 + aoff1) * 16, Ap + (size_t)64 * sg.lda);
        const __half* Bp = sg.B + (size_t)(lc * 32 + bk) * N + n0 + bcn * 8;
        CP16(bsb + (uint32_t)(buf * 512 + boff0) * 16, Bp);
        CP16(bsb + (uint32_t)(buf * 512 + boff1) * 16, Bp + (size_t)16 * N);
        asm volatile("cp.async.commit_group;\n");
        if (++lc == sg.kchunks) { lc = 0; ++ls; }
    };

    // prologue: fill 2 of 3 stages (all layers have tot >= 5)
    issue(0);
    issue(1);
    int issued = 2;
    int ibuf = 2;   // next buffer to fill
    int buf  = 0;   // buffer consumed this iteration

    for (int i = 0; i < tot; i++) {
        cp_wait<1>();          // retire the group for `buf` (invariant: 2 pending)
        __syncthreads();       // all warps done with buffer consumed last iter

        if (issued < tot) {
            issue(ibuf);       // overwrites buffer consumed at iter i-1 (safe)
            issued++;
            if (++ibuf == 3) ibuf = 0;
        } else {
            asm volatile("cp.async.commit_group;\n");   // empty group keeps invariant
        }

#pragma unroll
        for (int kk = 0; kk < 2; kk++) {
            // A fragments: 2 m16 tiles
            uint32_t a[2][4];
#pragma unroll
            for (int mi = 0; mi < 2; mi++) {
                const int mrow = wm + mi * 16 + (lane & 15);
                const int c    = kk * 2 + (lane >> 4);
                const int phys = mrow * 4 + (c ^ ((mrow >> 1) & 3));
                ldsm_x4(a[mi], asb + (uint32_t)(buf * 512 + phys) * 16);
            }
            // B fragments (4 groups of n16) + MMAs
#pragma unroll
            for (int j = 0; j < 4; j++) {
                uint32_t bb[4];
                const int krow = kk * 16 + (lane & 15);
                const int cn   = (wn >> 3) + j * 2 + (lane >> 4);
                const int phys = krow * 16 + (cn ^ (krow & 7));
                ldsm_x4_t(bb, bsb + (uint32_t)(buf * 512 + phys) * 16);
#pragma unroll
                for (int mi = 0; mi < 2; mi++) {
                    mma16816(d[mi][2 * j],     a[mi], bb[0], bb[1]);
                    mma16816(d[mi][2 * j + 1], a[mi], bb[2], bb[3]);
                }
            }
        }
        if (++buf == 3) buf = 0;
    }

    // ---- epilogue: bias + leaky-relu + fp16 store ----
#pragma unroll
    for (int mi = 0; mi < 2; mi++) {
#pragma unroll
        for (int j = 0; j < 8; j++) {
            const int col  = n0 + wn + j * 8 + (lane & 3) * 2;
            const float b0 = bias[col], b1 = bias[col + 1];
#pragma unroll
            for (int rh = 0; rh < 2; rh++) {
                const int row = m0 + wm + mi * 16 + (lane >> 2) + rh * 8;
                float v0 = d[mi][j][2 * rh]     + b0;
                float v1 = d[mi][j][2 * rh + 1] + b1;
                v0 = (v0 > 0.f) ? v0 : 0.02f * v0;
                v1 = (v1 > 0.f) ? v1 : 0.02f * v1;
                *reinterpret_cast<__half2*>(out + (size_t)row * N + col) =
                    __halves2half2(__float2half(v0), __float2half(v1));
            }
        }
    }
}

// ---------------------------------------------------------------------------
// Final layer: out[m] = h5[m,:] . W6 + b6   (128 -> 1)
// ---------------------------------------------------------------------------
__global__ void final_kernel(const __half* __restrict__ h5,
                             const float* __restrict__ W6,
                             const float* __restrict__ b6,
                             float* __restrict__ out)
{
    const int warp = threadIdx.x >> 5;
    const int lane = threadIdx.x & 31;
    const int m = blockIdx.x * 8 + warp;

    float s = 0.f;
#pragma unroll
    for (int j = 0; j < 4; j++) {
        const int c = 4 * lane + j;
        s = fmaf(__half2float(h5[(size_t)m * 128 + c]), W6[c], s);
    }
#pragma unroll
    for (int o = 16; o > 0; o >>= 1)
        s += __shfl_xor_sync(0xffffffffu, s, o);
    if (lane == 0) out[m] = s + b6[0];
}

// ---------------------------------------------------------------------------
// Launch
// ---------------------------------------------------------------------------
extern "C" void kernel_launch(void* const* d_in, const int* in_sizes, int n_in,
                              void* d_out, int out_size)
{
    (void)in_sizes; (void)n_in; (void)out_size;

    const int*   indices = (const int*)  d_in[0];
    const float* qp      = (const float*)d_in[1];
    const float* cpos    = (const float*)d_in[2];
    const float* codes   = (const float*)d_in[3];
    const float* W1 = (const float*)d_in[4];  const float* b1 = (const float*)d_in[5];
    const float* W2 = (const float*)d_in[6];  const float* b2 = (const float*)d_in[7];
    const float* W3 = (const float*)d_in[8];  const float* b3 = (const float*)d_in[9];
    const float* W4 = (const float*)d_in[10]; const float* b4 = (const float*)d_in[11];
    const float* W5 = (const float*)d_in[12]; const float* b5 = (const float*)d_in[13];
    const float* W6 = (const float*)d_in[14]; const float* b6 = (const float*)d_in[15];
    float* out = (float*)d_out;

    __half *x, *h1, *h2, *h3, *h4, *h5, *wq;
    cudaGetSymbolAddress((void**)&x,  g_x);
    cudaGetSymbolAddress((void**)&h1, g_h1); cudaGetSymbolAddress((void**)&h2, g_h2);
    cudaGetSymbolAddress((void**)&h3, g_h3); cudaGetSymbolAddress((void**)&h4, g_h4);
    cudaGetSymbolAddress((void**)&h5, g_h5); cudaGetSymbolAddress((void**)&wq, g_wq);

    // weight plane offsets (single fp16 plane per part)
    size_t off = 0;
    auto take = [&](size_t nelem) { __half* p = wq + off; off += nelem; return p; };
    __half* w1x = take((size_t)XK * 2048);
    __half* w2h = take((size_t)2048 * 1024);
    __half* w2x = take((size_t)XK * 1024);
    __half* w3h = take((size_t)1024 * 512);
    __half* w3x = take((size_t)XK * 512);
    __half* w4h = take((size_t)512 * 256);
    __half* w4x = take((size_t)XK * 256);
    __half* w5h = take((size_t)256 * 128);
    __half* w5x = take((size_t)XK * 128);

    // weight prep (fp32 -> fp16, x-part padded to 160 rows), 8 elems/thread
    auto prep = [&](const float* W, int K1, int N, __half* hh, __half* xh) {
        int tot = (K1 + XK) * (N >> 3);
        prep_w<<<(tot + 255) / 256, 256>>>(W, K1, N, hh, xh);
    };
    prep(W1, 0,    2048, w1x, w1x);
    prep(W2, 2048, 1024, w2h, w2x);
    prep(W3, 1024, 512,  w3h, w3x);
    prep(W4, 512,  256,  w4h, w4x);
    prep(W5, 256,  128,  w5h, w5x);

    // stage 1
    const int s1_smem = NK * ND * (int)sizeof(float) + 8 * NK * (int)sizeof(float);
    cudaFuncSetAttribute(stage1_kernel, cudaFuncAttributeMaxDynamicSharedMemorySize, s1_smem);
    stage1_kernel<<<dim3(NB, NP / PPB), 256, s1_smem>>>(indices, qp, cpos, codes);

    // layers:  act( h @ Wh + x @ Wx + b ) ; all activations single fp16 plane
    auto run = [&](int N, const float* bias,
                   __half* Ah, int K1, __half* Wh, __half* Wx, __half* Oh) {
        SegList SL;
        int n = 0;
        if (K1 > 0) SL.s[n++] = { Ah, Wh, K1, K1 >> 5 };
        SL.s[n++] = { x, Wx, XK, XK >> 5 };
        SL.n = n;
        mma_gemm<<<dim3(N / 128, NM / 128), 256>>>(SL, bias, N, Oh);
    };

    run(2048, b1, nullptr, 0,    nullptr, w1x, h1);
    run(1024, b2, h1, 2048, w2h, w2x, h2);
    run(512,  b3, h2, 1024, w3h, w3x, h3);
    run(256,  b4, h3, 512,  w4h, w4x, h4);
    run(128,  b5, h4, 256,  w5h, w5x, h5);

    // Final 128 -> 1 dot
    final_kernel<<<NM / 8, 256>>>(h5, W6, b6, out);
}

// round 17
// speedup vs baseline: 1.3005x; 1.0125x over previous
#include <cuda_runtime.h>
#include <cuda_fp16.h>
#include <stdint.h>

// ---------------------------------------------------------------------------
// Problem constants
// ---------------------------------------------------------------------------
#define NB   8
#define NP   8192
#define NM   (NB * NP)          // 65536 rows
#define NK   128                // codes per record
#define ND   128                // code dim
#define XK   160                // padded x K-dim (131 valid, rest zero) — mult of 32
#define PPB  128                // stage-1 points per block

// ---------------------------------------------------------------------------
// Scratch: single fp16 planes for x and h activations; fp16 weights.
// (h5 eliminated — final dot fused into layer-5 epilogue)
// ---------------------------------------------------------------------------
__device__ __half g_x [(size_t)NM * XK];
__device__ __half g_h1[(size_t)NM * 2048];
__device__ __half g_h2[(size_t)NM * 1024];
__device__ __half g_h3[(size_t)NM * 512];
__device__ __half g_h4[(size_t)NM * 256];
// fp16 weights (single plane): sum of (K1+160)*N over 5 layers = 3,420,160
__device__ __half g_wq[3500000];

// ---------------------------------------------------------------------------
// Helpers
// ---------------------------------------------------------------------------
__device__ __forceinline__ uint32_t smem_u32(const void* p)
{
    return (uint32_t)__cvta_generic_to_shared(p);
}

template<int Ngrp> __device__ __forceinline__ void cp_wait()
{
    asm volatile("cp.async.wait_group %0;\n" :: "n"(Ngrp));
}

#define CP16(dst_u32, src_ptr) \
    asm volatile("cp.async.cg.shared.global [%0], [%1], 16;\n" :: "r"(dst_u32), "l"(src_ptr))

__device__ __forceinline__ void ldsm_x4(uint32_t* r, uint32_t addr)
{
    asm volatile("ldmatrix.sync.aligned.m8n8.x4.shared.b16 {%0,%1,%2,%3}, [%4];\n"
                 : "=r"(r[0]), "=r"(r[1]), "=r"(r[2]), "=r"(r[3]) : "r"(addr));
}

__device__ __forceinline__ void ldsm_x4_t(uint32_t* r, uint32_t addr)
{
    asm volatile("ldmatrix.sync.aligned.m8n8.x4.trans.shared.b16 {%0,%1,%2,%3}, [%4];\n"
                 : "=r"(r[0]), "=r"(r[1]), "=r"(r[2]), "=r"(r[3]) : "r"(addr));
}

__device__ __forceinline__ void mma16816(float* d, const uint32_t* a, uint32_t b0, uint32_t b1)
{
    asm volatile(
        "mma.sync.aligned.m16n8k16.row.col.f32.f16.f16.f32 "
        "{%0,%1,%2,%3}, {%4,%5,%6,%7}, {%8,%9}, {%0,%1,%2,%3};\n"
        : "+f"(d[0]), "+f"(d[1]), "+f"(d[2]), "+f"(d[3])
        : "r"(a[0]), "r"(a[1]), "r"(a[2]), "r"(a[3]), "r"(b0), "r"(b1));
}

// ---------------------------------------------------------------------------
// Stage 1: inverse-square-distance weighted code interpolation -> x plane
// ---------------------------------------------------------------------------
__global__ void stage1_kernel(const int* __restrict__ indices,
                              const float* __restrict__ qp,
                              const float* __restrict__ codes_pos,
                              const float* __restrict__ codes)
{
    extern __shared__ float smem[];
    float4* bc4 = reinterpret_cast<float4*>(smem);   // [128 codes][32 float4]
    float*  ws  = smem + NK * ND;                    // [8 warps][128] weights

    const int b   = blockIdx.x;
    const int rec = indices[b];

    const float4* csrc = reinterpret_cast<const float4*>(codes + (size_t)rec * NK * ND);
    for (int i = threadIdx.x; i < NK * (ND / 4); i += blockDim.x)
        bc4[i] = csrc[i];
    __syncthreads();

    const int warp = threadIdx.x >> 5;
    const int lane = threadIdx.x & 31;

    const float* pbase = codes_pos + (size_t)rec * NK * 3;
    float cpx[4], cpy[4], cpz[4];
#pragma unroll
    for (int t = 0; t < 4; t++) {
        int k = lane + 32 * t;
        cpx[t] = pbase[k * 3 + 0];
        cpy[t] = pbase[k * 3 + 1];
        cpz[t] = pbase[k * 3 + 2];
    }

    float* wsw = ws + warp * NK;
    const int p0 = blockIdx.y * PPB;

    for (int pi = warp; pi < PPB; pi += 8) {
        const int m = b * NP + p0 + pi;
        const float qx = qp[(size_t)m * 3 + 0];
        const float qy = qp[(size_t)m * 3 + 1];
        const float qz = qp[(size_t)m * 3 + 2];

        float wsum = 0.f;
#pragma unroll
        for (int t = 0; t < 4; t++) {
            float dx = qx - cpx[t], dy = qy - cpy[t], dz = qz - cpz[t];
            float sq = dx * dx + dy * dy + dz * dz + 1e-16f;
            float w  = 1.0f / sq;
            wsw[lane + 32 * t] = w;
            wsum += w;
        }
        __syncwarp();
#pragma unroll
        for (int o = 16; o > 0; o >>= 1)
            wsum += __shfl_xor_sync(0xffffffffu, wsum, o);

        float4 acc = make_float4(0.f, 0.f, 0.f, 0.f);
#pragma unroll 4
        for (int k = 0; k < NK; k++) {
            const float  w = wsw[k];
            const float4 c = bc4[k * 32 + lane];
            acc.x = fmaf(w, c.x, acc.x);
            acc.y = fmaf(w, c.y, acc.y);
            acc.z = fmaf(w, c.z, acc.z);
            acc.w = fmaf(w, c.w, acc.w);
        }
        const float inv = 1.0f / wsum;

        __half* xh = g_x + (size_t)m * XK;
        float v[4] = { acc.x * inv, acc.y * inv, acc.z * inv, acc.w * inv };
#pragma unroll
        for (int j = 0; j < 4; j++)
            xh[4 * lane + j] = __float2half(v[j]);

        // tail cols 128..159: query point then zeros (one col per lane)
        {
            const int c = 128 + lane;
            float q = 0.f;
            if (lane == 0) q = qx; else if (lane == 1) q = qy; else if (lane == 2) q = qz;
            xh[c] = __float2half(q);
        }
        __syncwarp();
    }
}

// ---------------------------------------------------------------------------
// Fused weight prep: ALL 5 layers in one launch (8 elems/thread, vectorized).
// Block ranges select the layer via a prefix-offset table.
// ---------------------------------------------------------------------------
struct PrepParams {
    const float* W[5];
    __half*      hh[5];
    __half*      xh[5];
    int K1[5];
    int N[5];
    int blk_off[6];   // prefix block offsets; blk_off[5] = total blocks
};

__global__ void prep_all(const __grid_constant__ PrepParams P)
{
    int b = blockIdx.x;
    int l = 0;
#pragma unroll
    for (int i = 0; i < 5; i++) if (b >= P.blk_off[i + 1]) l = i + 1;

    const int K1 = P.K1[l], N = P.N[l];
    const int N8 = N >> 3;
    const int idx = (b - P.blk_off[l]) * 256 + threadIdx.x;
    if (idx >= (K1 + XK) * N8) return;
    const int r  = idx / N8;
    const int n0 = (idx - r * N8) << 3;
    const float* W = P.W[l];

    float f[8];
    __half* dst;
    if (r < K1) {
        const float4 a = *reinterpret_cast<const float4*>(W + (size_t)r * N + n0);
        const float4 c = *reinterpret_cast<const float4*>(W + (size_t)r * N + n0 + 4);
        f[0]=a.x; f[1]=a.y; f[2]=a.z; f[3]=a.w;
        f[4]=c.x; f[5]=c.y; f[6]=c.z; f[7]=c.w;
        dst = P.hh[l] + (size_t)r * N + n0;
    } else {
        const int r2 = r - K1;
        if (r2 < 131) {
            const float4 a = *reinterpret_cast<const float4*>(W + (size_t)(K1 + r2) * N + n0);
            const float4 c = *reinterpret_cast<const float4*>(W + (size_t)(K1 + r2) * N + n0 + 4);
            f[0]=a.x; f[1]=a.y; f[2]=a.z; f[3]=a.w;
            f[4]=c.x; f[5]=c.y; f[6]=c.z; f[7]=c.w;
        } else {
#pragma unroll
            for (int j = 0; j < 8; j++) f[j] = 0.f;
        }
        dst = P.xh[l] + (size_t)r2 * N + n0;
    }

    __half2 h2[4];
#pragma unroll
    for (int j = 0; j < 4; j++)
        h2[j] = __halves2half2(__float2half(f[2 * j]), __float2half(f[2 * j + 1]));
    *reinterpret_cast<uint4*>(dst) = *reinterpret_cast<const uint4*>(h2);
}

// ---------------------------------------------------------------------------
// Segmented fp16 tensor-core GEMM, fused bias + leaky-relu.
// Normal layers: fp16 store of activations.
// Last layer (w6 != nullptr): fused 128->1 dot with W6, fp32 store to outf.
// Mainloop byte-identical to proven R16 kernel (3-stage ring, single sync).
// ---------------------------------------------------------------------------
struct Seg { const __half* A; const __half* B; int lda; int kchunks; };
struct SegList { Seg s[2]; int n; };

__global__ __launch_bounds__(256, 2)
void mma_gemm(SegList SL, const float* __restrict__ bias, int N,
              __half* __restrict__ out,
              float* __restrict__ outf,
              const float* __restrict__ w6,
              const float* __restrict__ b6)
{
    __shared__ uint4 As4[3][512];   // [buf][m(128) x chunk(4)] xor-swizzled
    __shared__ uint4 Bs4[3][512];   // [buf][k(32) x chunk(16)] xor-swizzled
    __shared__ float dotbuf[128];

    const int t    = threadIdx.x;
    const int lane = t & 31;
    const int w    = t >> 5;
    const int wm   = (w & 3) * 32;   // warp M offset in tile
    const int wn   = (w >> 2) * 64;  // warp N offset in tile

    const int n0 = blockIdx.x * 128;
    const int m0 = blockIdx.y * 128;

    if (w6 && t < 128) dotbuf[t] = 0.f;   // ordered before use by in-loop syncs

    // loader thread-fixed coordinates
    const int am = t >> 2, ac = t & 3;
    const int aoff0 = am * 4        + (ac ^ ((am >> 1) & 3));
    const int aoff1 = (am + 64) * 4 + (ac ^ ((am >> 1) & 3));
    const int bk = t >> 4, bcn = t & 15;
    const int boff0 = bk * 16        + (bcn ^ (bk & 7));
    const int boff1 = (bk + 16) * 16 + (bcn ^ (bk & 7));

    const uint32_t asb = smem_u32(&As4[0][0]);
    const uint32_t bsb = smem_u32(&Bs4[0][0]);

    int tot = 0;
#pragma unroll
    for (int s = 0; s < 2; s++) if (s < SL.n) tot += SL.s[s].kchunks;

    float d[2][8][4];
#pragma unroll
    for (int i = 0; i < 2; i++)
#pragma unroll
        for (int j = 0; j < 8; j++)
#pragma unroll
            for (int q = 0; q < 4; q++) d[i][j][q] = 0.f;

    int ls = 0, lc = 0;   // next chunk to load: segment / chunk-in-segment

    auto issue = [&](int buf) {
        const Seg sg = SL.s[ls];
        const __half* Ap = sg.A + (size_t)(m0 + am) * sg.lda + lc * 32 + ac * 8;
        CP16(asb + (uint32_t)(buf * 512 + aoff0) * 16, Ap);
        CP16(asb + (uint32_t)(buf * 512 + aoff1) * 16, Ap + (size_t)64 * sg.lda);
        const __half* Bp = sg.B + (size_t)(lc * 32 + bk) * N + n0 + bcn * 8;
        CP16(bsb + (uint32_t)(buf * 512 + boff0) * 16, Bp);
        CP16(bsb + (uint32_t)(buf * 512 + boff1) * 16, Bp + (size_t)16 * N);
        asm volatile("cp.async.commit_group;\n");
        if (++lc == sg.kchunks) { lc = 0; ++ls; }
    };

    // prologue: fill 2 of 3 stages (all layers have tot >= 5)
    issue(0);
    issue(1);
    int issued = 2;
    int ibuf = 2;   // next buffer to fill
    int buf  = 0;   // buffer consumed this iteration

    for (int i = 0; i < tot; i++) {
        cp_wait<1>();          // retire the group for `buf` (invariant: 2 pending)
        __syncthreads();       // all warps done with buffer consumed last iter

        if (issued < tot) {
            issue(ibuf);       // overwrites buffer consumed at iter i-1 (safe)
            issued++;
            if (++ibuf == 3) ibuf = 0;
        } else {
            asm volatile("cp.async.commit_group;\n");   // empty group keeps invariant
        }

#pragma unroll
        for (int kk = 0; kk < 2; kk++) {
            uint32_t a[2][4];
#pragma unroll
            for (int mi = 0; mi < 2; mi++) {
                const int mrow = wm + mi * 16 + (lane & 15);
                const int c    = kk * 2 + (lane >> 4);
                const int phys = mrow * 4 + (c ^ ((mrow >> 1) & 3));
                ldsm_x4(a[mi], asb + (uint32_t)(buf * 512 + phys) * 16);
            }
#pragma unroll
            for (int j = 0; j < 4; j++) {
                uint32_t bb[4];
                const int krow = kk * 16 + (lane & 15);
                const int cn   = (wn >> 3) + j * 2 + (lane >> 4);
                const int phys = krow * 16 + (cn ^ (krow & 7));
                ldsm_x4_t(bb, bsb + (uint32_t)(buf * 512 + phys) * 16);
#pragma unroll
                for (int mi = 0; mi < 2; mi++) {
                    mma16816(d[mi][2 * j],     a[mi], bb[0], bb[1]);
                    mma16816(d[mi][2 * j + 1], a[mi], bb[2], bb[3]);
                }
            }
        }
        if (++buf == 3) buf = 0;
    }

    // ---- epilogue ----
    if (!w6) {
        // bias + leaky-relu + fp16 store
#pragma unroll
        for (int mi = 0; mi < 2; mi++) {
#pragma unroll
            for (int j = 0; j < 8; j++) {
                const int col  = n0 + wn + j * 8 + (lane & 3) * 2;
                const float b0 = bias[col], b1 = bias[col + 1];
#pragma unroll
                for (int rh = 0; rh < 2; rh++) {
                    const int row = m0 + wm + mi * 16 + (lane >> 2) + rh * 8;
                    float v0 = d[mi][j][2 * rh]     + b0;
                    float v1 = d[mi][j][2 * rh + 1] + b1;
                    v0 = (v0 > 0.f) ? v0 : 0.02f * v0;
                    v1 = (v1 > 0.f) ? v1 : 0.02f * v1;
                    *reinterpret_cast<__half2*>(out + (size_t)row * N + col) =
                        __halves2half2(__float2half(v0), __float2half(v1));
                }
            }
        }
    } else {
        // fused final: partial = sum_col act(v) * W6[col], reduce per row
        float part[2][2] = { {0.f, 0.f}, {0.f, 0.f} };
#pragma unroll
        for (int mi = 0; mi < 2; mi++) {
#pragma unroll
            for (int j = 0; j < 8; j++) {
                const int col  = wn + j * 8 + (lane & 3) * 2;   // n0 == 0 (N=128)
                const float b0 = bias[col], b1 = bias[col + 1];
                const float w0 = w6[col],  w1 = w6[col + 1];
#pragma unroll
                for (int rh = 0; rh < 2; rh++) {
                    float v0 = d[mi][j][2 * rh]     + b0;
                    float v1 = d[mi][j][2 * rh + 1] + b1;
                    v0 = (v0 > 0.f) ? v0 : 0.02f * v0;
                    v1 = (v1 > 0.f) ? v1 : 0.02f * v1;
                    part[mi][rh] = fmaf(v0, w0, fmaf(v1, w1, part[mi][rh]));
                }
            }
        }
#pragma unroll
        for (int mi = 0; mi < 2; mi++)
#pragma unroll
            for (int rh = 0; rh < 2; rh++)
                atomicAdd(&dotbuf[wm + mi * 16 + (lane >> 2) + rh * 8], part[mi][rh]);
        __syncthreads();
        if (t < 128) outf[m0 + t] = dotbuf[t] + b6[0];
    }
}

// ---------------------------------------------------------------------------
// Launch
// ---------------------------------------------------------------------------
extern "C" void kernel_launch(void* const* d_in, const int* in_sizes, int n_in,
                              void* d_out, int out_size)
{
    (void)in_sizes; (void)n_in; (void)out_size;

    const int*   indices = (const int*)  d_in[0];
    const float* qp      = (const float*)d_in[1];
    const float* cpos    = (const float*)d_in[2];
    const float* codes   = (const float*)d_in[3];
    const float* W1 = (const float*)d_in[4];  const float* b1 = (const float*)d_in[5];
    const float* W2 = (const float*)d_in[6];  const float* b2 = (const float*)d_in[7];
    const float* W3 = (const float*)d_in[8];  const float* b3 = (const float*)d_in[9];
    const float* W4 = (const float*)d_in[10]; const float* b4 = (const float*)d_in[11];
    const float* W5 = (const float*)d_in[12]; const float* b5 = (const float*)d_in[13];
    const float* W6 = (const float*)d_in[14]; const float* b6 = (const float*)d_in[15];
    float* out = (float*)d_out;

    __half *x, *h1, *h2, *h3, *h4, *wq;
    cudaGetSymbolAddress((void**)&x,  g_x);
    cudaGetSymbolAddress((void**)&h1, g_h1); cudaGetSymbolAddress((void**)&h2, g_h2);
    cudaGetSymbolAddress((void**)&h3, g_h3); cudaGetSymbolAddress((void**)&h4, g_h4);
    cudaGetSymbolAddress((void**)&wq, g_wq);

    // weight plane offsets (single fp16 plane per part)
    size_t off = 0;
    auto take = [&](size_t nelem) { __half* p = wq + off; off += nelem; return p; };
    __half* w1x = take((size_t)XK * 2048);
    __half* w2h = take((size_t)2048 * 1024);
    __half* w2x = take((size_t)XK * 1024);
    __half* w3h = take((size_t)1024 * 512);
    __half* w3x = take((size_t)XK * 512);
    __half* w4h = take((size_t)512 * 256);
    __half* w4x = take((size_t)XK * 256);
    __half* w5h = take((size_t)256 * 128);
    __half* w5x = take((size_t)XK * 128);

    // ---- fused weight prep: one launch for all 5 layers ----
    PrepParams P;
    const float* Ws[5]  = { W1, W2, W3, W4, W5 };
    __half* hhs[5]      = { w1x, w2h, w3h, w4h, w5h };   // hh unused for layer 0 (K1=0)
    __half* xhs[5]      = { w1x, w2x, w3x, w4x, w5x };
    int K1s[5]          = { 0, 2048, 1024, 512, 256 };
    int Ns[5]           = { 2048, 1024, 512, 256, 128 };
    P.blk_off[0] = 0;
    for (int l = 0; l < 5; l++) {
        P.W[l] = Ws[l]; P.hh[l] = hhs[l]; P.xh[l] = xhs[l];
        P.K1[l] = K1s[l]; P.N[l] = Ns[l];
        int blocks = ((K1s[l] + XK) * (Ns[l] >> 3) + 255) / 256;
        P.blk_off[l + 1] = P.blk_off[l] + blocks;
    }
    prep_all<<<P.blk_off[5], 256>>>(P);

    // ---- stage 1 ----
    const int s1_smem = NK * ND * (int)sizeof(float) + 8 * NK * (int)sizeof(float);
    cudaFuncSetAttribute(stage1_kernel, cudaFuncAttributeMaxDynamicSharedMemorySize, s1_smem);
    stage1_kernel<<<dim3(NB, NP / PPB), 256, s1_smem>>>(indices, qp, cpos, codes);

    // ---- layers ----
    auto run = [&](int N, const float* bias,
                   __half* Ah, int K1, __half* Wh, __half* Wx,
                   __half* Oh, float* Of, const float* w6p, const float* b6p) {
        SegList SL;
        int n = 0;
        if (K1 > 0) SL.s[n++] = { Ah, Wh, K1, K1 >> 5 };
        SL.s[n++] = { x, Wx, XK, XK >> 5 };
        SL.n = n;
        mma_gemm<<<dim3(N / 128, NM / 128), 256>>>(SL, bias, N, Oh, Of, w6p, b6p);
    };

    run(2048, b1, nullptr, 0,    nullptr, w1x, h1, nullptr, nullptr, nullptr);
    run(1024, b2, h1, 2048, w2h, w2x, h2, nullptr, nullptr, nullptr);
    run(512,  b3, h2, 1024, w3h, w3x, h3, nullptr, nullptr, nullptr);
    run(256,  b4, h3, 512,  w4h, w4x, h4, nullptr, nullptr, nullptr);
    run(128,  b5, h4, 256,  w5h, w5x, nullptr, out, W6, b6);   // fused final dot
}